// round 14
// baseline (speedup 1.0000x reference)
#include <cuda_runtime.h>
#include <math.h>

// Problem constants
#define Bc   256
#define Nc   256
#define Lc   1024
#define Dc   256
#define KQc  64
#define OUTc 64
#define NCH  8          // L / 128 logit chunks

using ull = unsigned long long;

// ---------------- scratch (device globals; no allocations allowed) ----------
__device__ float g_q[Bc * KQc];                      // scaled q  [B][KQ]
__device__ float g_k[(size_t)Nc * Lc * KQc];         // 64 MB     [N][L][KQ]
__device__ float g_v[(size_t)Nc * Lc * OUTc];        // 64 MB     [N][L][OUT]
__device__ float g_pmax[(size_t)Nc * Bc * NCH];      // partial max per l-chunk
__device__ float g_psum[(size_t)Nc * Bc * NCH];      // partial sumexp per l-chunk
__device__ float g_rmax[(size_t)Nc * Bc];            // global row max
__device__ float g_rrsum[(size_t)Nc * Bc];           // 1 / global sumexp

// ---------------- f32x2 helpers ---------------------------------------------
__device__ __forceinline__ ull bcast2(float x) {
    ull r; unsigned xi = __float_as_uint(x);
    asm("mov.b64 %0, {%1, %1};" : "=l"(r) : "r"(xi));
    return r;
}
__device__ __forceinline__ void ffma2(ull &d, ull a, ull b) {
    asm("fma.rn.f32x2 %0, %1, %2, %3;" : "=l"(d) : "l"(a), "l"(b), "l"(d));
}
__device__ __forceinline__ float2 unpack2(ull v) {
    unsigned lo, hi;
    asm("mov.b64 {%0, %1}, %2;" : "=r"(lo), "=r"(hi) : "l"(v));
    return make_float2(__uint_as_float(lo), __uint_as_float(hi));
}

// ---------------- K1: q = (queries @ Wq) * 1/sqrt(64) ------------------------
__global__ void k_qproj(const float* __restrict__ Q, const float* __restrict__ Wq) {
    int gid = blockIdx.x * 256 + threadIdx.x;      // 16384 outputs
    int b = gid >> 6, j = gid & 63;
    const float* qr = Q + (size_t)b * Dc;
    float acc = 0.f;
#pragma unroll 8
    for (int d = 0; d < Dc; ++d)
        acc = fmaf(qr[d], Wq[d * KQc + j], acc);
    g_q[gid] = acc * 0.125f;                       // fold softmax scale
}

// ---------------- K2: C[M,64] = A[M,256] @ W[256,64]  (k and v projections) --
// Block: 128 rows x 64 cols, K chunks of 32. 128 threads, thread tile 8r x 8c
// (8 cols as 4 f32x2 pairs). Conflict-free smem: AshT stride 129, Wsh stride 64.
__global__ void __launch_bounds__(128) k_proj(const float* __restrict__ A,
                                              const float* __restrict__ W,
                                              int which) {
    __shared__ float AshT[32 * 129];   // [32 d][128 row] (+pad)
    __shared__ float Wsh[32 * 64];     // [32 d][64 col]
    float* C = which ? g_v : g_k;

    const int tid = threadIdx.x;
    const int rg = tid >> 3;           // 16 row-groups of 8
    const int cg = tid & 7;            // 8 col-groups (2 cols x 4 strided)
    const size_t r0 = (size_t)blockIdx.x * 128;

    ull acc[8][4];
#pragma unroll
    for (int i = 0; i < 8; i++)
#pragma unroll
        for (int m = 0; m < 4; m++) acc[i][m] = 0ULL;

    for (int kk = 0; kk < Dc; kk += 32) {
        __syncthreads();
#pragma unroll
        for (int it = 0; it < 32; it++) {          // 128x32 A chunk, coalesced
            int idx = tid + it * 128;
            int d = idx & 31, row = idx >> 5;
            AshT[d * 129 + row] = A[(r0 + row) * Dc + kk + d];
        }
#pragma unroll
        for (int it = 0; it < 16; it++) {          // 32x64 W chunk
            int idx = tid + it * 128;
            int c = idx & 63, d = idx >> 6;
            Wsh[d * 64 + c] = W[(kk + d) * 64 + c];
        }
        __syncthreads();
#pragma unroll
        for (int d = 0; d < 32; ++d) {
            const float* ar = &AshT[d * 129 + rg * 8];
            const ull* wr = (const ull*)&Wsh[d * 64];
            ull w0 = wr[cg], w1 = wr[cg + 8], w2 = wr[cg + 16], w3 = wr[cg + 24];
#pragma unroll
            for (int i = 0; i < 8; i++) {
                ull a2 = bcast2(ar[i]);
                ffma2(acc[i][0], a2, w0); ffma2(acc[i][1], a2, w1);
                ffma2(acc[i][2], a2, w2); ffma2(acc[i][3], a2, w3);
            }
        }
    }
#pragma unroll
    for (int i = 0; i < 8; i++) {
        size_t row = r0 + rg * 8 + i;
        ull* cr = (ull*)&C[row * 64];
        cr[cg] = acc[i][0]; cr[cg + 8] = acc[i][1];
        cr[cg + 16] = acc[i][2]; cr[cg + 24] = acc[i][3];
    }
}

// ---------------- K3: raw logits + chunk-partial softmax stats ---------------
// Tile: 64 b x 128 l, K = KQ = 64 (single chunk). Writes RAW logits into the
// attn output buffer; per-(n,b,chunk) max / sumexp via width-16 shuffles.
// Dynamic smem: qsT [64][65] + ksT [64][130] = 49920 B.
__global__ void __launch_bounds__(128) k_logits(float* __restrict__ attn) {
    extern __shared__ float sh[];
    float* qsT = sh;                 // [64 d][64 b] stride 65
    float* ksT = sh + 64 * 65;       // [64 d][128 l] stride 130

    const int tid = threadIdx.x;
    const int rg = tid >> 4;         // 8 b-groups of 8
    const int cg = tid & 15;         // 16 l-groups (2 cols x 4 strided)
    const int l0 = blockIdx.x * 128;
    const int b0 = blockIdx.y * 64;
    const int n  = blockIdx.z;

#pragma unroll
    for (int it = 0; it < 32; it++) {               // 64x64 q tile
        int idx = tid + it * 128;
        int d = idx & 63, b = idx >> 6;
        qsT[d * 65 + b] = g_q[(b0 + b) * 64 + d];
    }
    const float* kbase = g_k + ((size_t)n * Lc + l0) * 64;
#pragma unroll
    for (int it = 0; it < 64; it++) {               // 128x64 k tile
        int idx = tid + it * 128;
        int d = idx & 63, l = idx >> 6;
        ksT[d * 130 + l] = kbase[(size_t)l * 64 + d];
    }
    __syncthreads();

    ull acc[8][4];
#pragma unroll
    for (int i = 0; i < 8; i++)
#pragma unroll
        for (int m = 0; m < 4; m++) acc[i][m] = 0ULL;

#pragma unroll
    for (int d = 0; d < 64; ++d) {
        const float* qr = &qsT[d * 65 + rg * 8];
        const ull* kr = (const ull*)&ksT[d * 130];
        ull w0 = kr[cg], w1 = kr[cg + 16], w2 = kr[cg + 32], w3 = kr[cg + 48];
#pragma unroll
        for (int i = 0; i < 8; i++) {
            ull a2 = bcast2(qr[i]);
            ffma2(acc[i][0], a2, w0); ffma2(acc[i][1], a2, w1);
            ffma2(acc[i][2], a2, w2); ffma2(acc[i][3], a2, w3);
        }
    }

#pragma unroll
    for (int i = 0; i < 8; i++) {
        int b = b0 + rg * 8 + i;
        float2 x0 = unpack2(acc[i][0]), x1 = unpack2(acc[i][1]);
        float2 x2 = unpack2(acc[i][2]), x3 = unpack2(acc[i][3]);
        float mx = fmaxf(fmaxf(fmaxf(x0.x, x0.y), fmaxf(x1.x, x1.y)),
                         fmaxf(fmaxf(x2.x, x2.y), fmaxf(x3.x, x3.y)));
#pragma unroll
        for (int off = 8; off; off >>= 1)
            mx = fmaxf(mx, __shfl_xor_sync(0xffffffffu, mx, off, 16));
        float s = __expf(x0.x - mx) + __expf(x0.y - mx)
                + __expf(x1.x - mx) + __expf(x1.y - mx)
                + __expf(x2.x - mx) + __expf(x2.y - mx)
                + __expf(x3.x - mx) + __expf(x3.y - mx);
#pragma unroll
        for (int off = 8; off; off >>= 1)
            s += __shfl_xor_sync(0xffffffffu, s, off, 16);
        if (cg == 0) {
            size_t sidx = ((size_t)n * Bc + b) * NCH + blockIdx.x;
            g_pmax[sidx] = mx; g_psum[sidx] = s;
        }
        ull* orow = (ull*)(attn + ((size_t)n * Bc + b) * Lc + l0);
        orow[cg] = acc[i][0]; orow[cg + 16] = acc[i][1];
        orow[cg + 32] = acc[i][2]; orow[cg + 48] = acc[i][3];
    }
}

// ---------------- K4: combine chunk stats -> global max, 1/sum ---------------
__global__ void k_combine() {
    int t = blockIdx.x * 256 + threadIdx.x;        // 65536 = N*B rows
    const float* pm = g_pmax + (size_t)t * NCH;
    const float* ps = g_psum + (size_t)t * NCH;
    float gm = pm[0];
#pragma unroll
    for (int c = 1; c < NCH; c++) gm = fmaxf(gm, pm[c]);
    float rs = 0.f;
#pragma unroll
    for (int c = 0; c < NCH; c++) rs += ps[c] * __expf(pm[c] - gm);
    g_rmax[t] = gm;
    g_rrsum[t] = 1.0f / rs;
}

// ---------------- K5: normalize attn (in place) + result = attn @ v ----------
// Tile: 64 b x 64 o per (n, b-tile) block, L chunks of 64.
// Reads raw logits, writes normalized softmax back (the required attn output),
// and accumulates result[b][n][o] with f32x2 FMAs. Thread tile 8b x 4o.
__global__ void __launch_bounds__(128) k_out(float* __restrict__ attn,
                                             float* __restrict__ result) {
    __shared__ float pT[64 * 65];    // [64 l][64 b]
    __shared__ float vsh[64 * 66];   // [64 l][64 o]
    __shared__ float mrow[64], rrow[64];

    const int tid = threadIdx.x;
    const int rg = tid >> 4;         // 8 b-groups of 8
    const int cg = tid & 15;         // 16 o-groups (2 cols x 2 strided)
    const int b0 = blockIdx.x * 64;
    const int n  = blockIdx.y;

    if (tid < 64) {
        size_t ri = (size_t)n * Bc + b0 + tid;
        mrow[tid] = g_rmax[ri];
        rrow[tid] = g_rrsum[ri];
    }

    ull acc[8][2];
#pragma unroll
    for (int i = 0; i < 8; i++) { acc[i][0] = 0ULL; acc[i][1] = 0ULL; }

    for (int lc = 0; lc < Lc; lc += 64) {
        __syncthreads();
#pragma unroll
        for (int it = 0; it < 32; it++) {           // 64b x 64l logits chunk
            int idx = tid + it * 128;
            int l = idx & 63, b = idx >> 6;
            float* gp = attn + ((size_t)n * Bc + b0 + b) * Lc + lc + l;
            float p = __expf(*gp - mrow[b]) * rrow[b];
            *gp = p;                                // final normalized attn
            pT[l * 65 + b] = p;
        }
#pragma unroll
        for (int it = 0; it < 32; it++) {           // 64l x 64o v chunk
            int idx = tid + it * 128;
            int o = idx & 63, l = idx >> 6;
            vsh[l * 66 + o] = g_v[((size_t)n * Lc + lc + l) * 64 + o];
        }
        __syncthreads();
#pragma unroll
        for (int l = 0; l < 64; ++l) {
            const float* pr = &pT[l * 65 + rg * 8];
            const ull* vr = (const ull*)&vsh[l * 66];
            ull w0 = vr[cg], w1 = vr[cg + 16];
#pragma unroll
            for (int i = 0; i < 8; i++) {
                ull a2 = bcast2(pr[i]);
                ffma2(acc[i][0], a2, w0);
                ffma2(acc[i][1], a2, w1);
            }
        }
    }
#pragma unroll
    for (int i = 0; i < 8; i++) {
        size_t b = b0 + rg * 8 + i;
        ull* orow = (ull*)(result + (b * Nc + n) * OUTc);
        orow[cg] = acc[i][0];
        orow[cg + 16] = acc[i][1];
    }
}

// ---------------- launch -----------------------------------------------------
extern "C" void kernel_launch(void* const* d_in, const int* in_sizes, int n_in,
                              void* d_out, int out_size) {
    const float* queries = (const float*)d_in[0];   // [B, D]
    const float* keys    = (const float*)d_in[1];   // [N, L, D]
    const float* values  = (const float*)d_in[2];   // [N, L, D]
    const float* Wq      = (const float*)d_in[3];   // [D, KQ]
    const float* Wk      = (const float*)d_in[4];   // [D, KQ]
    const float* Wv      = (const float*)d_in[5];   // [D, OUT]

    float* result = (float*)d_out;                          // [B, N, OUT]
    float* attn   = result + (size_t)Bc * Nc * OUTc;        // [N, B, L]

    // k_logits needs 49920 B dynamic smem (> 48 KB default)
    cudaFuncSetAttribute(k_logits, cudaFuncAttributeMaxDynamicSharedMemorySize, 49920);

    k_qproj<<<(Bc * KQc) / 256, 256>>>(queries, Wq);
    k_proj<<<(Nc * Lc) / 128, 128>>>(keys, Wk, 0);
    k_proj<<<(Nc * Lc) / 128, 128>>>(values, Wv, 1);
    k_logits<<<dim3(Lc / 128, Bc / 64, Nc), 128, 49920>>>(attn);
    k_combine<<<(Nc * Bc) / 256, 256>>>();
    k_out<<<dim3(Bc / 64, Nc), 128>>>(attn, result);
}

// round 15
// speedup vs baseline: 1.0644x; 1.0644x over previous
#include <cuda_runtime.h>
#include <math.h>

// Problem constants
#define Bc   256
#define Nc   256
#define Lc   1024
#define Dc   256
#define NCH  8          // L / 128 logit chunks

using ull = unsigned long long;

// ---------------- scratch (device globals; no allocations allowed) ----------
__device__ float g_q[Bc * 64];                       // scaled q  [B][KQ]
__device__ float g_k[(size_t)Nc * Lc * 64];          // 64 MB     [N][L][KQ]
__device__ float g_v[(size_t)Nc * Lc * 64];          // 64 MB     [N][L][OUT]
__device__ float g_pmax[(size_t)Nc * Bc * NCH];      // partial max per l-chunk
__device__ float g_psum[(size_t)Nc * Bc * NCH];      // partial sumexp per l-chunk
__device__ float g_rmax[(size_t)Nc * Bc];            // global row max
__device__ float g_rrsum[(size_t)Nc * Bc];           // 1 / global sumexp

// ---------------- f32x2 helpers ---------------------------------------------
__device__ __forceinline__ ull bcast2(float x) {
    ull r; unsigned xi = __float_as_uint(x);
    asm("mov.b64 %0, {%1, %1};" : "=l"(r) : "r"(xi));
    return r;
}
__device__ __forceinline__ void ffma2(ull &d, ull a, ull b) {
    asm("fma.rn.f32x2 %0, %1, %2, %3;" : "=l"(d) : "l"(a), "l"(b), "l"(d));
}
__device__ __forceinline__ float2 unpack2(ull v) {
    unsigned lo, hi;
    asm("mov.b64 {%0, %1}, %2;" : "=r"(lo), "=r"(hi) : "l"(v));
    return make_float2(__uint_as_float(lo), __uint_as_float(hi));
}

// ---------------- K1: q = (queries @ Wq) * 1/sqrt(64) ------------------------
__global__ void k_qproj(const float* __restrict__ Q, const float* __restrict__ Wq) {
    int gid = blockIdx.x * 256 + threadIdx.x;      // 16384 outputs
    int b = gid >> 6, j = gid & 63;
    const float* qr = Q + (size_t)b * Dc;
    float acc = 0.f;
#pragma unroll 8
    for (int d = 0; d < Dc; ++d)
        acc = fmaf(qr[d], Wq[d * 64 + j], acc);
    g_q[gid] = acc * 0.125f;                       // fold softmax scale
}

// ---------------- K2: k/v projections, merged: C[M,64] = A[M,256] @ W --------
// Block tile 128r x 64c, 128 threads, thread tile 8r x 8c (rows strided by 16).
// A-side stored DUPLICATED in smem ([d][2r]=[d][2r+1]) so the inner loop is
// pure LDS.64 + FFMA2 (no packing MOVs). All inner LDS conflict-free.
__global__ void __launch_bounds__(128) k_proj(const float* __restrict__ keys,
                                              const float* __restrict__ values,
                                              const float* __restrict__ Wk,
                                              const float* __restrict__ Wv) {
    __shared__ float AshD[32 * 258];   // [32 d][128 rows duplicated (+pad)]
    __shared__ float Wsh[32 * 64];     // [32 d][64 col]

    const int which = blockIdx.y;
    const float* A = which ? values : keys;
    const float* W = which ? Wv : Wk;
    float* C = which ? g_v : g_k;

    const int tid = threadIdx.x;
    const int rg = tid >> 3;           // 16 row groups (rows rg + 16*i)
    const int cg = tid & 7;            // 8 col groups (pairs cg + 8*m)
    const size_t r0 = (size_t)blockIdx.x * 128;

    ull acc[8][4];
#pragma unroll
    for (int i = 0; i < 8; i++)
#pragma unroll
        for (int m = 0; m < 4; m++) acc[i][m] = 0ULL;

    for (int kk = 0; kk < Dc; kk += 32) {
        __syncthreads();
#pragma unroll
        for (int it = 0; it < 32; it++) {          // 128x32 A chunk, coalesced
            int idx = tid + it * 128;
            int d = idx & 31, r = idx >> 5;
            *(ull*)&AshD[d * 258 + 2 * r] = bcast2(A[(r0 + r) * Dc + kk + d]);
        }
#pragma unroll
        for (int it = 0; it < 16; it++) {          // 32x64 W chunk
            int idx = tid + it * 128;
            int c = idx & 63, d = idx >> 6;
            Wsh[d * 64 + c] = W[(kk + d) * 64 + c];
        }
        __syncthreads();
#pragma unroll
        for (int d = 0; d < 32; ++d) {
            const ull* ar = (const ull*)&AshD[d * 258];
            const ull* wr = (const ull*)&Wsh[d * 64];
            ull w0 = wr[cg], w1 = wr[cg + 8], w2 = wr[cg + 16], w3 = wr[cg + 24];
#pragma unroll
            for (int i = 0; i < 8; i++) {
                ull a2 = ar[rg + 16 * i];
                ffma2(acc[i][0], a2, w0); ffma2(acc[i][1], a2, w1);
                ffma2(acc[i][2], a2, w2); ffma2(acc[i][3], a2, w3);
            }
        }
    }
#pragma unroll
    for (int i = 0; i < 8; i++) {
        size_t row = r0 + rg + 16 * i;
        ull* cr = (ull*)&C[row * 64];
        cr[cg] = acc[i][0]; cr[cg + 8] = acc[i][1];
        cr[cg + 16] = acc[i][2]; cr[cg + 24] = acc[i][3];
    }
}

// ---------------- K3: raw logits + chunk-partial softmax stats ---------------
// Tile 64b x 128l, K=64 in two 32-chunks (smem 33 KB -> 5 blocks/SM).
// q-side duplicated in smem; FFMA2 vector dim = l. Writes RAW logits into the
// attn output buffer; per-(n,b,chunk) max / sumexp via width-16 shuffles.
__global__ void __launch_bounds__(128) k_logits(float* __restrict__ attn) {
    __shared__ float qsD[32 * 130];    // [32 d][64 b duplicated (+pad)]
    __shared__ float ksT[32 * 130];    // [32 d][128 l (+pad)]

    const int tid = threadIdx.x;
    const int rg = tid >> 4;           // 8 b-groups of 8 rows
    const int cg = tid & 15;           // 16 l-groups (pairs cg + 16*m)
    const int l0 = blockIdx.x * 128;
    const int b0 = blockIdx.y * 64;
    const int n  = blockIdx.z;

    ull acc[8][4];
#pragma unroll
    for (int i = 0; i < 8; i++)
#pragma unroll
        for (int m = 0; m < 4; m++) acc[i][m] = 0ULL;

    for (int kk = 0; kk < 64; kk += 32) {
        __syncthreads();
#pragma unroll
        for (int it = 0; it < 16; it++) {           // 64b x 32d q chunk (dup)
            int idx = tid + it * 128;
            int d = idx & 31, b = idx >> 5;
            *(ull*)&qsD[d * 130 + 2 * b] = bcast2(g_q[(b0 + b) * 64 + kk + d]);
        }
        const float* kb = g_k + ((size_t)n * Lc + l0) * 64 + kk;
#pragma unroll
        for (int it = 0; it < 32; it++) {           // 128l x 32d k chunk
            int idx = tid + it * 128;
            int d = idx & 31, l = idx >> 5;
            ksT[d * 130 + l] = kb[(size_t)l * 64 + d];
        }
        __syncthreads();
#pragma unroll
        for (int d = 0; d < 32; ++d) {
            const ull* qr = (const ull*)&qsD[d * 130];
            const ull* kr = (const ull*)&ksT[d * 130];
            ull w0 = kr[cg], w1 = kr[cg + 16], w2 = kr[cg + 32], w3 = kr[cg + 48];
#pragma unroll
            for (int i = 0; i < 8; i++) {
                ull a2 = qr[rg * 8 + i];
                ffma2(acc[i][0], a2, w0); ffma2(acc[i][1], a2, w1);
                ffma2(acc[i][2], a2, w2); ffma2(acc[i][3], a2, w3);
            }
        }
    }

#pragma unroll
    for (int i = 0; i < 8; i++) {
        int b = b0 + rg * 8 + i;
        float2 x0 = unpack2(acc[i][0]), x1 = unpack2(acc[i][1]);
        float2 x2 = unpack2(acc[i][2]), x3 = unpack2(acc[i][3]);
        float mx = fmaxf(fmaxf(fmaxf(x0.x, x0.y), fmaxf(x1.x, x1.y)),
                         fmaxf(fmaxf(x2.x, x2.y), fmaxf(x3.x, x3.y)));
#pragma unroll
        for (int off = 8; off; off >>= 1)
            mx = fmaxf(mx, __shfl_xor_sync(0xffffffffu, mx, off, 16));
        float s = __expf(x0.x - mx) + __expf(x0.y - mx)
                + __expf(x1.x - mx) + __expf(x1.y - mx)
                + __expf(x2.x - mx) + __expf(x2.y - mx)
                + __expf(x3.x - mx) + __expf(x3.y - mx);
#pragma unroll
        for (int off = 8; off; off >>= 1)
            s += __shfl_xor_sync(0xffffffffu, s, off, 16);
        if (cg == 0) {
            size_t sidx = ((size_t)n * Bc + b) * NCH + blockIdx.x;
            g_pmax[sidx] = mx; g_psum[sidx] = s;
        }
        ull* orow = (ull*)(attn + ((size_t)n * Bc + b) * Lc + l0);
        orow[cg] = acc[i][0]; orow[cg + 16] = acc[i][1];
        orow[cg + 32] = acc[i][2]; orow[cg + 48] = acc[i][3];
    }
}

// ---------------- K4: combine chunk stats -> global max, 1/sum ---------------
__global__ void k_combine() {
    int t = blockIdx.x * 256 + threadIdx.x;        // 65536 = N*B rows
    const float* pm = g_pmax + (size_t)t * NCH;
    const float* ps = g_psum + (size_t)t * NCH;
    float gm = pm[0];
#pragma unroll
    for (int c = 1; c < NCH; c++) gm = fmaxf(gm, pm[c]);
    float rs = 0.f;
#pragma unroll
    for (int c = 0; c < NCH; c++) rs += ps[c] * __expf(pm[c] - gm);
    g_rmax[t] = gm;
    g_rrsum[t] = 1.0f / rs;
}

// ---------------- K5: normalize attn (in place) + result = attn @ v ----------
// Tile 64b x 64o, 128 threads, thread tile 4b x 8o. L chunks of 32.
// p-side duplicated in smem. smem 26 KB, small acc -> high occupancy.
__global__ void __launch_bounds__(128) k_out(float* __restrict__ attn,
                                             float* __restrict__ result) {
    __shared__ float pD[32 * 130];     // [32 l][64 b duplicated (+pad)]
    __shared__ float vsh[32 * 66];     // [32 l][64 o (+pad)]
    __shared__ float mrow[64], rrow[64];

    const int tid = threadIdx.x;
    const int rg = tid >> 3;           // 16 b-groups of 4 rows
    const int cg = tid & 7;            // 8 o-groups (pairs cg + 8*m)
    const int b0 = blockIdx.x * 64;
    const int n  = blockIdx.y;

    if (tid < 64) {
        size_t ri = (size_t)n * Bc + b0 + tid;
        mrow[tid] = g_rmax[ri];
        rrow[tid] = g_rrsum[ri];
    }

    ull acc[4][4];
#pragma unroll
    for (int i = 0; i < 4; i++)
#pragma unroll
        for (int m = 0; m < 4; m++) acc[i][m] = 0ULL;

    for (int lc = 0; lc < Lc; lc += 32) {
        __syncthreads();
#pragma unroll
        for (int it = 0; it < 16; it++) {           // 64b x 32l logits chunk
            int idx = tid + it * 128;
            int l = idx & 31, b = idx >> 5;
            float* gp = attn + ((size_t)n * Bc + b0 + b) * Lc + lc + l;
            float p = __expf(*gp - mrow[b]) * rrow[b];
            *gp = p;                                // final normalized attn
            *(ull*)&pD[l * 130 + 2 * b] = bcast2(p);
        }
        const float* vb = g_v + ((size_t)n * Lc + lc) * 64;
#pragma unroll
        for (int it = 0; it < 16; it++) {           // 32l x 64o v chunk
            int idx = tid + it * 128;
            int o = idx & 63, l = idx >> 6;
            vsh[l * 66 + o] = vb[(size_t)l * 64 + o];
        }
        __syncthreads();
#pragma unroll
        for (int l = 0; l < 32; ++l) {
            const ull* pr = (const ull*)&pD[l * 130];
            const ull* vr = (const ull*)&vsh[l * 66];
            ull w0 = vr[cg], w1 = vr[cg + 8], w2 = vr[cg + 16], w3 = vr[cg + 24];
#pragma unroll
            for (int i = 0; i < 4; i++) {
                ull a2 = pr[rg * 4 + i];
                ffma2(acc[i][0], a2, w0); ffma2(acc[i][1], a2, w1);
                ffma2(acc[i][2], a2, w2); ffma2(acc[i][3], a2, w3);
            }
        }
    }
#pragma unroll
    for (int i = 0; i < 4; i++) {
        size_t b = b0 + rg * 4 + i;
        ull* orow = (ull*)&result[(b * Nc + n) * 64];
        orow[cg] = acc[i][0]; orow[cg + 8] = acc[i][1];
        orow[cg + 16] = acc[i][2]; orow[cg + 24] = acc[i][3];
    }
}

// ---------------- launch -----------------------------------------------------
extern "C" void kernel_launch(void* const* d_in, const int* in_sizes, int n_in,
                              void* d_out, int out_size) {
    const float* queries = (const float*)d_in[0];   // [B, D]
    const float* keys    = (const float*)d_in[1];   // [N, L, D]
    const float* values  = (const float*)d_in[2];   // [N, L, D]
    const float* Wq      = (const float*)d_in[3];   // [D, KQ]
    const float* Wk      = (const float*)d_in[4];   // [D, KQ]
    const float* Wv      = (const float*)d_in[5];   // [D, OUT]

    float* result = (float*)d_out;                          // [B, N, OUT]
    float* attn   = result + (size_t)Bc * Nc * 64;          // [N, B, L]

    k_qproj<<<(Bc * 64) / 256, 256>>>(queries, Wq);
    k_proj<<<dim3((Nc * Lc) / 128, 2), 128>>>(keys, values, Wk, Wv);
    k_logits<<<dim3(Lc / 128, Bc / 64, Nc), 128>>>(attn);
    k_combine<<<(Nc * Bc) / 256, 256>>>();
    k_out<<<dim3(Bc / 64, Nc), 128>>>(attn, result);
}